// round 1
// baseline (speedup 1.0000x reference)
#include <cuda_runtime.h>
#include <math.h>

#define B 8
#define SL 4096
#define D 128
#define NH 8
#define NB 64       // buckets per hash
#define NC 512      // n_chunks = NH * NB
#define BS 64       // bucket/chunk size
#define NSL (NH*SL) // 32768
#define PAD 132     // smem row stride (floats), multiple of 4 for float4

#define MNEG (-3.402823466e38f)

// ---------------- scratch (device globals; no runtime allocation) ----------
__device__ int   g_buckets[B][NH][SL];   // bucket incl. h*NB offset
__device__ int   g_hist[B][NC];
__device__ int   g_boff[B][NC];
__device__ int   g_sticker[B][NSL];      // sorted tickers
__device__ int   g_undo[B][NSL];         // ticker -> sorted pos
__device__ int   g_loc1[B][NH][SL];
__device__ int   g_loc2[B][NH][SL];
__device__ float g_so[B][NSL][D];        // sorted attention output (134 MB)
__device__ float g_slog[B][NSL];         // sorted lse

// ---------------- kernels --------------------------------------------------
__global__ void k_zero_hist() {
    g_hist[blockIdx.x][threadIdx.x] = 0;
}

// buckets + histogram. grid (SL/256, NH, B), block 256
__global__ void k_buckets(const float* __restrict__ qk, const float* __restrict__ rot) {
    __shared__ float rs[128 * 32];
    int b = blockIdx.z, h = blockIdx.y;
    int tid = threadIdx.x;
    for (int i = tid; i < 128 * 32; i += 256) {
        int d = i >> 5, n = i & 31;
        rs[i] = rot[(d * NH + h) * 32 + n];
    }
    __syncthreads();
    int s = blockIdx.x * 256 + tid;
    const float* q = qk + ((size_t)b * SL + s) * D;
    float acc[32];
#pragma unroll
    for (int n = 0; n < 32; n++) acc[n] = 0.f;
    for (int d = 0; d < 128; d++) {
        float qv = q[d];
        const float* r = &rs[d * 32];
#pragma unroll
        for (int n = 0; n < 32; n++) acc[n] += qv * r[n];
    }
    // argmax over [acc, -acc], first-max-wins (matches jnp.argmax)
    float best = acc[0]; int idx = 0;
#pragma unroll
    for (int n = 1; n < 32; n++) if (acc[n] > best) { best = acc[n]; idx = n; }
#pragma unroll
    for (int n = 0; n < 32; n++) if (-acc[n] > best) { best = -acc[n]; idx = 32 + n; }
    int bucket = idx + h * NB;
    g_buckets[b][h][s] = bucket;
    atomicAdd(&g_hist[b][bucket], 1);
}

// exclusive scan of 512 bins per batch. grid B, 1 thread does the work.
__global__ void k_prefix() {
    int b = blockIdx.x;
    if (threadIdx.x == 0) {
        int run = 0;
        for (int i = 0; i < NC; i++) { g_boff[b][i] = run; run += g_hist[b][i]; }
    }
}

// stable counting-sort scatter. grid (NH, B), block 64 (one thread per bucket)
__global__ void k_scatter() {
    int h = blockIdx.x, b = blockIdx.y;
    int k = threadIdx.x;
    int bk = h * NB + k;
    int pos = g_boff[b][bk];
    const int* bb = &g_buckets[b][h][0];
    for (int t = 0; t < SL; t++) {
        if (bb[t] == bk) {
            int j = h * SL + t;
            g_sticker[b][pos] = j;
            g_undo[b][j] = pos;
            pos++;
        }
    }
}

// duplicate-detection location codes. grid (B*NSL/256), block 256
__global__ void k_loc() {
    int idx = blockIdx.x * 256 + threadIdx.x;
    int b = idx / NSL, r = idx % NSL;
    int h = r >> 12, t = r & (SL - 1);
    int chunk = g_undo[b][r] >> 6;
    int bucket = g_buckets[b][h][t];
    g_loc1[b][h][t] = bucket * NC + chunk;
    g_loc2[b][h][t] = bucket * NC + ((chunk + 1) & (NC - 1));
}

// chunked attention. grid (NC, B), block 256, dynamic smem
extern __shared__ float smem[];
__global__ void k_attn(const float* __restrict__ qk, const float* __restrict__ v) {
    int n = blockIdx.x, b = blockIdx.y;
    int tid = threadIdx.x;
    int warp = tid >> 5, lane = tid & 31;

    float* qs   = smem;                 // 64*PAD
    float* ks   = qs + 64 * PAD;        // 128*PAD (unit-normalized keys)
    float* vs   = ks + 128 * PAD;       // 128*PAD
    float* dots = vs + 128 * PAD;       // 64*PAD
    int* qt  = (int*)(dots + 64 * PAD); // 64
    int* qb  = qt + 64;                 // 64
    int* kt  = qb + 64;                 // 128
    int* kb  = kt + 128;                // 128
    int* ql1 = kb + 128;                // 64*8
    int* kl1 = ql1 + 64 * 8;            // 128*9
    int* kl2 = kl1 + 128 * 9;           // 128*9

    int prev = (n + NC - 1) & (NC - 1);

    // load kv rows (current chunk: z<64, previous chunk: z>=64)
    for (int z = warp; z < 128; z += 8) {
        int p = (z < 64) ? (n * BS + z) : (prev * BS + (z - 64));
        int tf = g_sticker[b][p];
        int t = tf & (SL - 1), h = tf >> 12;
        const float* src = qk + ((size_t)b * SL + t) * D;
        float4 x = ((const float4*)src)[lane];
        float ss = x.x * x.x + x.y * x.y + x.z * x.z + x.w * x.w;
#pragma unroll
        for (int o = 16; o > 0; o >>= 1) ss += __shfl_xor_sync(0xffffffffu, ss, o);
        float inv = 1.f / fmaxf(sqrtf(ss), 1e-12f);
        float4 kn = make_float4(x.x * inv, x.y * inv, x.z * inv, x.w * inv);
        ((float4*)(ks + z * PAD))[lane] = kn;
        const float* vsrc = v + ((size_t)b * SL + t) * D;
        ((float4*)(vs + z * PAD))[lane] = ((const float4*)vsrc)[lane];
        if (lane == 0) { kt[z] = t; kb[z] = g_buckets[b][h][t]; }
        if (lane < 8)       kl1[z * 9 + lane]     = g_loc1[b][lane][t];
        else if (lane < 16) kl2[z * 9 + lane - 8] = g_loc2[b][lane - 8][t];
    }
    // load q rows
    for (int s = warp; s < 64; s += 8) {
        int p = n * BS + s;
        int tf = g_sticker[b][p];
        int t = tf & (SL - 1), h = tf >> 12;
        const float* src = qk + ((size_t)b * SL + t) * D;
        ((float4*)(qs + s * PAD))[lane] = ((const float4*)src)[lane];
        if (lane == 0) { qt[s] = t; qb[s] = g_buckets[b][h][t]; }
        if (lane < 8) ql1[s * 8 + lane] = g_loc1[b][lane][t];
    }
    __syncthreads();

    // dots: thread owns 4 consecutive z, strides over s
    int zq = (tid & 31) * 4;
    int s0 = tid >> 5;
    for (int s = s0; s < 64; s += 8) {
        float a0 = 0, a1 = 0, a2 = 0, a3 = 0;
        const float* qrow = qs + s * PAD;
        const float* k0 = ks + (zq + 0) * PAD;
        const float* k1 = ks + (zq + 1) * PAD;
        const float* k2 = ks + (zq + 2) * PAD;
        const float* k3 = ks + (zq + 3) * PAD;
#pragma unroll 8
        for (int d = 0; d < 128; d += 4) {
            float4 q4 = *(const float4*)(qrow + d);
            float4 x0 = *(const float4*)(k0 + d);
            float4 x1 = *(const float4*)(k1 + d);
            float4 x2 = *(const float4*)(k2 + d);
            float4 x3 = *(const float4*)(k3 + d);
            a0 += q4.x * x0.x + q4.y * x0.y + q4.z * x0.z + q4.w * x0.w;
            a1 += q4.x * x1.x + q4.y * x1.y + q4.z * x1.z + q4.w * x1.w;
            a2 += q4.x * x2.x + q4.y * x2.y + q4.z * x2.z + q4.w * x2.w;
            a3 += q4.x * x3.x + q4.y * x3.y + q4.z * x3.z + q4.w * x3.w;
        }
        dots[s * PAD + zq + 0] = a0;
        dots[s * PAD + zq + 1] = a1;
        dots[s * PAD + zq + 2] = a2;
        dots[s * PAD + zq + 3] = a3;
    }
    __syncthreads();

    // scale + masks + dup-correction (reference order: causal, self, bucket, dup)
    const float scale = 0.08838834764831845f;  // 128^-0.5
    for (int pr = tid; pr < 64 * 128; pr += 256) {
        int s = pr >> 7, z = pr & 127;
        float val = dots[s * PAD + z] * scale;
        int qtv = qt[s], ktv = kt[z];
        if (qtv < ktv)  val = MNEG;
        if (qtv == ktv) val = -10000.f;
        if (qb[s] != kb[z]) val = MNEG;
        int cnt = 0;
#pragma unroll
        for (int i = 0; i < 8; i++) {
            int l = ql1[s * 8 + i];
            cnt += (l == kl1[z * 9 + i]) + (l == kl2[z * 9 + i]);
        }
        val -= logf((float)cnt + 1e-9f);
        dots[s * PAD + z] = val;
    }
    __syncthreads();

    // row softmax + lse (64 rows, one thread each)
    if (tid < 64) {
        float* row = dots + tid * PAD;
        float m = MNEG;
        for (int z = 0; z < 128; z++) m = fmaxf(m, row[z]);
        float sum = 0.f;
        for (int z = 0; z < 128; z++) { float e = expf(row[z] - m); row[z] = e; sum += e; }
        g_slog[b][n * BS + tid] = m + logf(sum);
        float rs = 1.f / sum;
        for (int z = 0; z < 128; z++) row[z] *= rs;
    }
    __syncthreads();

    // bo = probs @ v, write to sorted output buffer
    int dq = (tid & 31) * 4;
    for (int s = s0; s < 64; s += 8) {
        float ax = 0, ay = 0, az = 0, aw = 0;
        const float* prow = dots + s * PAD;
#pragma unroll 4
        for (int z = 0; z < 128; z++) {
            float p = prow[z];
            float4 vv = *(const float4*)(vs + z * PAD + dq);
            ax += p * vv.x; ay += p * vv.y; az += p * vv.z; aw += p * vv.w;
        }
        float4 acc = make_float4(ax, ay, az, aw);
        *(float4*)(&g_so[b][n * BS + s][dq]) = acc;
    }
}

// cross-hash-round combine. grid (SL, B), block 128 (one thread per dim)
__global__ void k_combine(float* __restrict__ out) {
    int t = blockIdx.x, b = blockIdx.y;
    int d = threadIdx.x;
    int p[NH];
    float l[NH];
    float m = MNEG;
#pragma unroll
    for (int h = 0; h < NH; h++) {
        p[h] = g_undo[b][h * SL + t];
        l[h] = g_slog[b][p[h]];
        m = fmaxf(m, l[h]);
    }
    float sum = 0.f;
#pragma unroll
    for (int h = 0; h < NH; h++) { l[h] = expf(l[h] - m); sum += l[h]; }
    float inv = 1.f / sum;
    float acc = 0.f;
#pragma unroll
    for (int h = 0; h < NH; h++) acc += l[h] * inv * g_so[b][p[h]][d];
    out[((size_t)b * SL + t) * D + d] = acc;
}

// ---------------- launch ----------------------------------------------------
extern "C" void kernel_launch(void* const* d_in, const int* in_sizes, int n_in,
                              void* d_out, int out_size) {
    (void)in_sizes; (void)n_in; (void)out_size;
    const float* qk  = (const float*)d_in[0];
    const float* v   = (const float*)d_in[1];
    const float* rot = (const float*)d_in[2];
    float* out = (float*)d_out;

    // dynamic smem: floats (64+128+128+64)*PAD + ints (64+64+128+128+512+1152+1152)
    const int smem_bytes = (384 * PAD) * 4 + 3200 * 4;  // 215,552 B
    cudaFuncSetAttribute(k_attn, cudaFuncAttributeMaxDynamicSharedMemorySize, smem_bytes);

    k_zero_hist<<<B, NC>>>();
    k_buckets<<<dim3(SL / 256, NH, B), 256>>>(qk, rot);
    k_prefix<<<B, 1>>>();
    k_scatter<<<dim3(NH, B), 64>>>();
    k_loc<<<(B * NSL) / 256, 256>>>();
    k_attn<<<dim3(NC, B), 256, smem_bytes>>>(qk, v);
    k_combine<<<dim3(SL, B), 128>>>(out);
}

// round 2
// speedup vs baseline: 3.3728x; 3.3728x over previous
#include <cuda_runtime.h>
#include <math.h>

#define B 8
#define SL 4096
#define D 128
#define NH 8
#define NB 64       // buckets per hash
#define NC 512      // n_chunks = NH * NB
#define BS 64       // bucket/chunk size
#define NSL (NH*SL) // 32768
#define PAD 132     // smem row stride (floats); 132 % 32 == 4 -> conflict-free column access

#define MNEG (-3.402823466e38f)

// ---------------- scratch (device globals; no runtime allocation) ----------
__device__ int   g_buckets[B][NH][SL];   // bucket incl. h*NB offset
__device__ int   g_hist[B][NC];
__device__ int   g_boff[B][NC];
__device__ int   g_sticker[B][NSL];      // sorted tickers
__device__ int   g_undo[B][NSL];         // ticker -> sorted pos
__device__ int   g_loc1[B][NH][SL];
__device__ int   g_loc2[B][NH][SL];
__device__ float g_so[B][NSL][D];        // sorted attention output
__device__ float g_slog[B][NSL];         // sorted lse

// ---------------- kernels --------------------------------------------------
__global__ void k_zero_hist() {
    g_hist[blockIdx.x][threadIdx.x] = 0;
}

// buckets + histogram. grid (SL/256, NH, B), block 256. Coalesced via smem staging.
__global__ void k_buckets(const float* __restrict__ qk, const float* __restrict__ rot) {
    __shared__ float rs[32 * 32];      // d-tile (32) x n (32)
    __shared__ float qt_[256 * 33];    // tokens x d-tile, stride 33 (conflict-free)
    int b = blockIdx.z, h = blockIdx.y;
    int tid = threadIdx.x;
    int s0 = blockIdx.x * 256;

    float acc[32];
#pragma unroll
    for (int n = 0; n < 32; n++) acc[n] = 0.f;

    for (int d0 = 0; d0 < 128; d0 += 32) {
        for (int i = tid; i < 32 * 32; i += 256) {
            int dd = i >> 5, nn = i & 31;
            rs[i] = rot[((size_t)(d0 + dd) * NH + h) * 32 + nn];
        }
        for (int i = tid; i < 256 * 32; i += 256) {
            int r = i >> 5, c = i & 31;
            qt_[r * 33 + c] = qk[((size_t)b * SL + s0 + r) * D + d0 + c];
        }
        __syncthreads();
#pragma unroll 4
        for (int dd = 0; dd < 32; dd++) {
            float qv = qt_[tid * 33 + dd];
            const float* r = &rs[dd * 32];
#pragma unroll
            for (int n = 0; n < 32; n++) acc[n] += qv * r[n];
        }
        __syncthreads();
    }
    // argmax over [acc, -acc], first-max-wins (matches jnp.argmax)
    float best = acc[0]; int idx = 0;
#pragma unroll
    for (int n = 1; n < 32; n++) if (acc[n] > best) { best = acc[n]; idx = n; }
#pragma unroll
    for (int n = 0; n < 32; n++) if (-acc[n] > best) { best = -acc[n]; idx = 32 + n; }
    int s = s0 + tid;
    int bucket = idx + h * NB;
    g_buckets[b][h][s] = bucket;
    atomicAdd(&g_hist[b][bucket], 1);
}

// exclusive scan of 512 bins per batch. grid B, block NC. Hillis-Steele.
__global__ void k_prefix() {
    __shared__ int sh[NC];
    int b = blockIdx.x, tid = threadIdx.x;
    int v = g_hist[b][tid];
    sh[tid] = v;
    __syncthreads();
#pragma unroll
    for (int off = 1; off < NC; off <<= 1) {
        int x = (tid >= off) ? sh[tid - off] : 0;
        __syncthreads();
        sh[tid] += x;
        __syncthreads();
    }
    g_boff[b][tid] = sh[tid] - v;   // exclusive
}

// stable counting-sort scatter: one warp per bucket, ballot+popc ranks.
// grid (NC, B), block 32
__global__ void k_scatter() {
    int bk = blockIdx.x, b = blockIdx.y;
    int h = bk >> 6;
    int lane = threadIdx.x;
    int pos = g_boff[b][bk];
    const int* bb = &g_buckets[b][h][0];
    for (int base = 0; base < SL; base += 32) {
        int t = base + lane;
        bool m = (bb[t] == bk);
        unsigned bal = __ballot_sync(0xffffffffu, m);
        if (m) {
            int r = __popc(bal & ((1u << lane) - 1));
            int j = h * SL + t;
            g_sticker[b][pos + r] = j;
            g_undo[b][j] = pos + r;
        }
        pos += __popc(bal);
    }
}

// duplicate-detection location codes. grid (B*NSL/256), block 256
__global__ void k_loc() {
    int idx = blockIdx.x * 256 + threadIdx.x;
    int b = idx / NSL, r = idx % NSL;
    int h = r >> 12, t = r & (SL - 1);
    int chunk = g_undo[b][r] >> 6;
    int bucket = g_buckets[b][h][t];
    g_loc1[b][h][t] = bucket * NC + chunk;
    g_loc2[b][h][t] = bucket * NC + ((chunk + 1) & (NC - 1));
}

// chunked attention. grid (NC, B), block 512, dynamic smem.
// 16 warps; warp w owns query rows {w, w+16, w+32, w+48}.
extern __shared__ float smem[];
__global__ void __launch_bounds__(512, 1)
k_attn(const float* __restrict__ qk, const float* __restrict__ v) {
    int n = blockIdx.x, b = blockIdx.y;
    int tid = threadIdx.x;
    int warp = tid >> 5, lane = tid & 31;

    float* qs = smem;              // 64*PAD  (q rows; reused as probs)
    float* ks = qs + 64 * PAD;     // 128*PAD (unit-normalized keys)
    float* vs = ks + 128 * PAD;    // 128*PAD
    int* qt = (int*)(vs + 128 * PAD); // 64
    int* qb = qt + 64;                // 64
    int* kt = qb + 64;                // 128
    int* kb = kt + 128;               // 128
    int* ql1 = kb + 128;              // 64*8
    int* kl  = ql1 + 512;             // 128*18  (loc1/loc2 interleaved pairs)

    int prev = (n + NC - 1) & (NC - 1);

    // ---- load kv rows (z<64 current chunk, z>=64 previous chunk) ----
    for (int z = warp; z < 128; z += 16) {
        int p = (z < 64) ? (n * BS + z) : (prev * BS + (z - 64));
        int tf = g_sticker[b][p];
        int t = tf & (SL - 1), h = tf >> 12;
        const float* src = qk + ((size_t)b * SL + t) * D;
        float4 x = ((const float4*)src)[lane];
        float ss = x.x * x.x + x.y * x.y + x.z * x.z + x.w * x.w;
#pragma unroll
        for (int o = 16; o > 0; o >>= 1) ss += __shfl_xor_sync(0xffffffffu, ss, o);
        float inv = 1.f / fmaxf(sqrtf(ss), 1e-12f);
        ((float4*)(ks + z * PAD))[lane] = make_float4(x.x * inv, x.y * inv, x.z * inv, x.w * inv);
        const float* vsrc = v + ((size_t)b * SL + t) * D;
        ((float4*)(vs + z * PAD))[lane] = ((const float4*)vsrc)[lane];
        if (lane == 0) { kt[z] = t; kb[z] = g_buckets[b][h][t]; }
        if (lane < 8)       kl[z * 18 + 2 * lane]           = g_loc1[b][lane][t];
        else if (lane < 16) kl[z * 18 + 2 * (lane - 8) + 1] = g_loc2[b][lane - 8][t];
    }
    // ---- load q rows (each warp loads exactly its own compute rows) ----
    for (int s = warp; s < 64; s += 16) {
        int p = n * BS + s;
        int tf = g_sticker[b][p];
        int t = tf & (SL - 1), h = tf >> 12;
        ((float4*)(qs + s * PAD))[lane] = ((const float4*)(qk + ((size_t)b * SL + t) * D))[lane];
        if (lane == 0) { qt[s] = t; qb[s] = g_buckets[b][h][t]; }
        if (lane < 8) ql1[s * 8 + lane] = g_loc1[b][lane][t];
    }
    __syncthreads();   // the only block-wide sync

    // ---- QK^T: 4 rows x 4 z register tile (z = lane + 32*i) ----
    float acc[4][4];
#pragma unroll
    for (int j = 0; j < 4; j++)
#pragma unroll
        for (int i = 0; i < 4; i++) acc[j][i] = 0.f;

    for (int d = 0; d < 128; d += 4) {
        float4 kx[4];
#pragma unroll
        for (int i = 0; i < 4; i++)
            kx[i] = *(const float4*)(ks + (lane + 32 * i) * PAD + d);
#pragma unroll
        for (int j = 0; j < 4; j++) {
            float4 q4 = *(const float4*)(qs + (warp + 16 * j) * PAD + d);
#pragma unroll
            for (int i = 0; i < 4; i++)
                acc[j][i] += q4.x * kx[i].x + q4.y * kx[i].y + q4.z * kx[i].z + q4.w * kx[i].w;
        }
    }

    // ---- masks + dup correction (reference order: causal, self, bucket, dup) ----
    const float scale = 0.08838834764831845f;  // 128^-0.5
#pragma unroll
    for (int j = 0; j < 4; j++) {
        int s = warp + 16 * j;
        int qtv = qt[s], qbv = qb[s];
        int ql[8];
#pragma unroll
        for (int m = 0; m < 8; m++) ql[m] = ql1[s * 8 + m];
#pragma unroll
        for (int i = 0; i < 4; i++) {
            int z = lane + 32 * i;
            float val = acc[j][i] * scale;
            int ktv = kt[z];
            if (qtv < ktv)  val = MNEG;
            if (qtv == ktv) val = -10000.f;
            if (qbv != kb[z]) val = MNEG;
            int cnt = 0;
#pragma unroll
            for (int m = 0; m < 8; m++) {
                int2 lp = *(const int2*)&kl[z * 18 + 2 * m];
                cnt += (ql[m] == lp.x) + (ql[m] == lp.y);
            }
            val -= logf((float)cnt + 1e-9f);
            acc[j][i] = val;
        }
    }

    // ---- per-row softmax via warp shuffles; probs overwrite qs rows ----
#pragma unroll
    for (int j = 0; j < 4; j++) {
        float m = fmaxf(fmaxf(acc[j][0], acc[j][1]), fmaxf(acc[j][2], acc[j][3]));
#pragma unroll
        for (int o = 16; o > 0; o >>= 1) m = fmaxf(m, __shfl_xor_sync(0xffffffffu, m, o));
        float e[4]; float sum = 0.f;
#pragma unroll
        for (int i = 0; i < 4; i++) { e[i] = expf(acc[j][i] - m); sum += e[i]; }
#pragma unroll
        for (int o = 16; o > 0; o >>= 1) sum += __shfl_xor_sync(0xffffffffu, sum, o);
        int s = warp + 16 * j;
        if (lane == 0) g_slog[b][n * BS + s] = m + logf(sum);
        float inv = 1.f / sum;
#pragma unroll
        for (int i = 0; i < 4; i++) qs[s * PAD + lane + 32 * i] = e[i] * inv;
    }
    // no sync needed: each warp reads only its own prob rows below

    // ---- PV: 4 rows x 4 d-cols register tile ----
    float o[4][4];
#pragma unroll
    for (int j = 0; j < 4; j++)
#pragma unroll
        for (int i = 0; i < 4; i++) o[j][i] = 0.f;
    int dd = lane * 4;
    for (int z = 0; z < 128; z++) {
        float4 vv = *(const float4*)(vs + z * PAD + dd);
#pragma unroll
        for (int j = 0; j < 4; j++) {
            float p = qs[(warp + 16 * j) * PAD + z];
            o[j][0] += p * vv.x; o[j][1] += p * vv.y;
            o[j][2] += p * vv.z; o[j][3] += p * vv.w;
        }
    }
#pragma unroll
    for (int j = 0; j < 4; j++) {
        int s = warp + 16 * j;
        *(float4*)(&g_so[b][n * BS + s][dd]) = make_float4(o[j][0], o[j][1], o[j][2], o[j][3]);
    }
}

// cross-hash-round combine. grid (SL, B), block 128 (one thread per dim)
__global__ void k_combine(float* __restrict__ out) {
    int t = blockIdx.x, b = blockIdx.y;
    int d = threadIdx.x;
    int p[NH];
    float l[NH];
    float m = MNEG;
#pragma unroll
    for (int h = 0; h < NH; h++) {
        p[h] = g_undo[b][h * SL + t];
        l[h] = g_slog[b][p[h]];
        m = fmaxf(m, l[h]);
    }
    float sum = 0.f;
#pragma unroll
    for (int h = 0; h < NH; h++) { l[h] = expf(l[h] - m); sum += l[h]; }
    float inv = 1.f / sum;
    float acc = 0.f;
#pragma unroll
    for (int h = 0; h < NH; h++) acc += l[h] * inv * g_so[b][p[h]][d];
    out[((size_t)b * SL + t) * D + d] = acc;
}

// ---------------- launch ----------------------------------------------------
extern "C" void kernel_launch(void* const* d_in, const int* in_sizes, int n_in,
                              void* d_out, int out_size) {
    (void)in_sizes; (void)n_in; (void)out_size;
    const float* qk  = (const float*)d_in[0];
    const float* v   = (const float*)d_in[1];
    const float* rot = (const float*)d_in[2];
    float* out = (float*)d_out;

    // floats: (64+128+128)*PAD ; ints: 64+64+128+128+512+128*18 = 3200
    const int smem_bytes = (320 * PAD) * 4 + 3200 * 4;  // 181,760 B
    cudaFuncSetAttribute(k_attn, cudaFuncAttributeMaxDynamicSharedMemorySize, smem_bytes);

    k_zero_hist<<<B, NC>>>();
    k_buckets<<<dim3(SL / 256, NH, B), 256>>>(qk, rot);
    k_prefix<<<B, NC>>>();
    k_scatter<<<dim3(NC, B), 32>>>();
    k_loc<<<(B * NSL) / 256, 256>>>();
    k_attn<<<dim3(NC, B), 512, smem_bytes>>>(qk, v);
    k_combine<<<dim3(SL, B), 128>>>(out);
}

// round 3
// speedup vs baseline: 3.5716x; 1.0589x over previous
#include <cuda_runtime.h>
#include <math.h>

#define B 8
#define SL 4096
#define D 128
#define NH 8
#define NB 64       // buckets per hash
#define NC 512      // n_chunks = NH * NB
#define BS 64       // bucket/chunk size
#define NSL (NH*SL) // 32768
#define PAD 132     // smem row stride (floats); %32==4 -> conflict-free rows & cols

#define MNEG (-3.402823466e38f)

typedef unsigned long long ull;

// packed 2x fp32 fma (Blackwell f32x2 pipe; PTX-only)
__device__ __forceinline__ void fma2(ull& d, ull a, ull b) {
    asm("fma.rn.f32x2 %0, %1, %2, %0;" : "+l"(d) : "l"(a), "l"(b));
}
__device__ __forceinline__ ull pack2(float lo, float hi) {
    ull r; asm("mov.b64 %0, {%1, %2};" : "=l"(r) : "f"(lo), "f"(hi)); return r;
}
__device__ __forceinline__ float2 unpack2(ull v) {
    float2 r; asm("mov.b64 {%0, %1}, %2;" : "=f"(r.x), "=f"(r.y) : "l"(v)); return r;
}

// ---------------- scratch (device globals; no runtime allocation) ----------
__device__ int   g_buckets[B][NH][SL];   // bucket incl. h*NB offset
__device__ int   g_hist[B][NC];
__device__ int   g_boff[B][NC];
__device__ int   g_sticker[B][NSL];      // sorted tickers
__device__ int   g_undo[B][NSL];         // ticker -> sorted pos
__device__ int   g_loc1[B][NH][SL];
__device__ int   g_loc2[B][NH][SL];
__device__ float g_so[B][NSL][D];        // sorted attention output
__device__ float g_slog[B][NSL];         // sorted lse

// ---------------- kernels --------------------------------------------------
__global__ void k_zero_hist() {
    g_hist[blockIdx.x][threadIdx.x] = 0;
}

// buckets + histogram. grid (SL/256, NH, B), block 256.
__global__ void k_buckets(const float* __restrict__ qk, const float* __restrict__ rot) {
    __shared__ float rs[32 * 32];      // d-tile (32) x n (32)
    __shared__ float qt_[256 * 33];    // tokens x d-tile, stride 33
    int b = blockIdx.z, h = blockIdx.y;
    int tid = threadIdx.x;
    int s0 = blockIdx.x * 256;

    ull acc2[16];
#pragma unroll
    for (int n = 0; n < 16; n++) acc2[n] = 0ull;

    for (int d0 = 0; d0 < 128; d0 += 32) {
        for (int i = tid; i < 32 * 32; i += 256) {
            int dd = i >> 5, nn = i & 31;
            rs[i] = rot[((size_t)(d0 + dd) * NH + h) * 32 + nn];
        }
        for (int i = tid; i < 256 * 32; i += 256) {
            int r = i >> 5, c = i & 31;
            qt_[r * 33 + c] = qk[((size_t)b * SL + s0 + r) * D + d0 + c];
        }
        __syncthreads();
#pragma unroll 4
        for (int dd = 0; dd < 32; dd++) {
            float qv = qt_[tid * 33 + dd];
            ull qq = pack2(qv, qv);
            const ull* r2 = (const ull*)&rs[dd * 32];
#pragma unroll
            for (int n = 0; n < 16; n++) fma2(acc2[n], qq, r2[n]);
        }
        __syncthreads();
    }
    float acc[32];
#pragma unroll
    for (int n = 0; n < 16; n++) {
        float2 p = unpack2(acc2[n]);
        acc[2 * n] = p.x; acc[2 * n + 1] = p.y;
    }
    // argmax over [acc, -acc], first-max-wins (matches jnp.argmax)
    float best = acc[0]; int idx = 0;
#pragma unroll
    for (int n = 1; n < 32; n++) if (acc[n] > best) { best = acc[n]; idx = n; }
#pragma unroll
    for (int n = 0; n < 32; n++) if (-acc[n] > best) { best = -acc[n]; idx = 32 + n; }
    int s = s0 + tid;
    int bucket = idx + h * NB;
    g_buckets[b][h][s] = bucket;
    atomicAdd(&g_hist[b][bucket], 1);
}

// exclusive scan of 512 bins per batch. grid B, block NC. Hillis-Steele.
__global__ void k_prefix() {
    __shared__ int sh[NC];
    int b = blockIdx.x, tid = threadIdx.x;
    int v = g_hist[b][tid];
    sh[tid] = v;
    __syncthreads();
#pragma unroll
    for (int off = 1; off < NC; off <<= 1) {
        int x = (tid >= off) ? sh[tid - off] : 0;
        __syncthreads();
        sh[tid] += x;
        __syncthreads();
    }
    g_boff[b][tid] = sh[tid] - v;   // exclusive
}

// stable counting-sort scatter: 4 warps per bucket, two-pass (count, scatter).
// grid (NC, B), block 128
__global__ void k_scatter() {
    int bk = blockIdx.x, b = blockIdx.y;
    int h = bk >> 6;
    int warp = threadIdx.x >> 5, lane = threadIdx.x & 31;
    const int* bb = &g_buckets[b][h][0];
    int t0 = warp * (SL / 4);

    __shared__ int wc[4];
    int cnt = 0;
    for (int base = 0; base < SL / 4; base += 32) {
        bool m = (bb[t0 + base + lane] == bk);
        cnt += __popc(__ballot_sync(0xffffffffu, m));
    }
    if (lane == 0) wc[warp] = cnt;
    __syncthreads();

    int pos = g_boff[b][bk];
#pragma unroll
    for (int w = 0; w < 4; w++) if (w < warp) pos += wc[w];

    for (int base = 0; base < SL / 4; base += 32) {
        int t = t0 + base + lane;
        bool m = (bb[t] == bk);
        unsigned bal = __ballot_sync(0xffffffffu, m);
        if (m) {
            int r = __popc(bal & ((1u << lane) - 1));
            int j = h * SL + t;
            g_sticker[b][pos + r] = j;
            g_undo[b][j] = pos + r;
        }
        pos += __popc(bal);
    }
}

// duplicate-detection location codes. grid (B*NSL/256), block 256
__global__ void k_loc() {
    int idx = blockIdx.x * 256 + threadIdx.x;
    int b = idx / NSL, r = idx % NSL;
    int h = r >> 12, t = r & (SL - 1);
    int chunk = g_undo[b][r] >> 6;
    int bucket = g_buckets[b][h][t];
    g_loc1[b][h][t] = bucket * NC + chunk;
    g_loc2[b][h][t] = bucket * NC + ((chunk + 1) & (NC - 1));
}

// chunked attention. grid (NC, B), block 512, dynamic smem.
// 16 warps; warp w owns query rows {w, w+16, w+32, w+48}.
extern __shared__ float smem[];
__global__ void __launch_bounds__(512, 1)
k_attn(const float* __restrict__ qk, const float* __restrict__ v) {
    int n = blockIdx.x, b = blockIdx.y;
    int tid = threadIdx.x;
    int warp = tid >> 5, lane = tid & 31;

    float* qs = smem;              // 64*PAD  (q rows; reused as probs)
    float* ks = qs + 64 * PAD;     // 128*PAD (unit-normalized keys)
    float* vs = ks + 128 * PAD;    // 128*PAD
    int* qt = (int*)(vs + 128 * PAD); // 64
    int* qb = qt + 64;                // 64
    int* kt = qb + 64;                // 128
    int* kb = kt + 128;               // 128
    int* ql1 = kb + 128;              // 64*8
    int* kl  = ql1 + 512;             // 128*18  (loc1/loc2 interleaved pairs)

    int prev = (n + NC - 1) & (NC - 1);

    // ---- load kv rows (z<64 current chunk, z>=64 previous chunk) ----
    for (int z = warp; z < 128; z += 16) {
        int p = (z < 64) ? (n * BS + z) : (prev * BS + (z - 64));
        int tf = g_sticker[b][p];
        int t = tf & (SL - 1), h = tf >> 12;
        const float* src = qk + ((size_t)b * SL + t) * D;
        float4 x = ((const float4*)src)[lane];
        float ss = x.x * x.x + x.y * x.y + x.z * x.z + x.w * x.w;
#pragma unroll
        for (int o = 16; o > 0; o >>= 1) ss += __shfl_xor_sync(0xffffffffu, ss, o);
        float inv = 1.f / fmaxf(sqrtf(ss), 1e-12f);
        ((float4*)(ks + z * PAD))[lane] = make_float4(x.x * inv, x.y * inv, x.z * inv, x.w * inv);
        const float* vsrc = v + ((size_t)b * SL + t) * D;
        ((float4*)(vs + z * PAD))[lane] = ((const float4*)vsrc)[lane];
        if (lane == 0) { kt[z] = t; kb[z] = g_buckets[b][h][t]; }
        if (lane < 8)       kl[z * 18 + 2 * lane]           = g_loc1[b][lane][t];
        else if (lane < 16) kl[z * 18 + 2 * (lane - 8) + 1] = g_loc2[b][lane - 8][t];
    }
    // ---- load q rows ----
    for (int s = warp; s < 64; s += 16) {
        int p = n * BS + s;
        int tf = g_sticker[b][p];
        int t = tf & (SL - 1), h = tf >> 12;
        ((float4*)(qs + s * PAD))[lane] = ((const float4*)(qk + ((size_t)b * SL + t) * D))[lane];
        if (lane == 0) { qt[s] = t; qb[s] = g_buckets[b][h][t]; }
        if (lane < 8) ql1[s * 8 + lane] = g_loc1[b][lane][t];
    }
    __syncthreads();   // the only block-wide sync

    // ---- QK^T: 4 rows x 4 z tile, packed f32x2 over even/odd d ----
    ull acc2[4][4];
#pragma unroll
    for (int j = 0; j < 4; j++)
#pragma unroll
        for (int i = 0; i < 4; i++) acc2[j][i] = 0ull;

    for (int d = 0; d < 128; d += 4) {
        ulonglong2 kx[4];
#pragma unroll
        for (int i = 0; i < 4; i++)
            kx[i] = *(const ulonglong2*)(ks + (lane + 32 * i) * PAD + d);
#pragma unroll
        for (int j = 0; j < 4; j++) {
            ulonglong2 q2 = *(const ulonglong2*)(qs + (warp + 16 * j) * PAD + d);
#pragma unroll
            for (int i = 0; i < 4; i++) {
                fma2(acc2[j][i], q2.x, kx[i].x);
                fma2(acc2[j][i], q2.y, kx[i].y);
            }
        }
    }
    float acc[4][4];
#pragma unroll
    for (int j = 0; j < 4; j++)
#pragma unroll
        for (int i = 0; i < 4; i++) {
            float2 p = unpack2(acc2[j][i]);
            acc[j][i] = p.x + p.y;
        }

    // ---- masks + dup correction (reference order: causal, self, bucket, dup) ----
    const float scale = 0.08838834764831845f;  // 128^-0.5
#pragma unroll
    for (int j = 0; j < 4; j++) {
        int s = warp + 16 * j;
        int qtv = qt[s], qbv = qb[s];
        int ql[8];
#pragma unroll
        for (int m = 0; m < 8; m++) ql[m] = ql1[s * 8 + m];
#pragma unroll
        for (int i = 0; i < 4; i++) {
            int z = lane + 32 * i;
            float val = acc[j][i] * scale;
            int ktv = kt[z];
            if (qtv < ktv)  val = MNEG;
            if (qtv == ktv) val = -10000.f;
            if (qbv != kb[z]) val = MNEG;
            int cnt = 0;
#pragma unroll
            for (int m = 0; m < 8; m++) {
                int2 lp = *(const int2*)&kl[z * 18 + 2 * m];
                cnt += (ql[m] == lp.x) + (ql[m] == lp.y);
            }
            val -= logf((float)cnt + 1e-9f);
            acc[j][i] = val;
        }
    }

    // ---- per-row softmax via warp shuffles; probs overwrite qs rows ----
#pragma unroll
    for (int j = 0; j < 4; j++) {
        float m = fmaxf(fmaxf(acc[j][0], acc[j][1]), fmaxf(acc[j][2], acc[j][3]));
#pragma unroll
        for (int o = 16; o > 0; o >>= 1) m = fmaxf(m, __shfl_xor_sync(0xffffffffu, m, o));
        float e[4]; float sum = 0.f;
#pragma unroll
        for (int i = 0; i < 4; i++) { e[i] = expf(acc[j][i] - m); sum += e[i]; }
#pragma unroll
        for (int o = 16; o > 0; o >>= 1) sum += __shfl_xor_sync(0xffffffffu, sum, o);
        int s = warp + 16 * j;
        if (lane == 0) g_slog[b][n * BS + s] = m + logf(sum);
        float inv = 1.f / sum;
#pragma unroll
        for (int i = 0; i < 4; i++) qs[s * PAD + lane + 32 * i] = e[i] * inv;
    }
    __syncwarp();  // warp-private rows: intra-warp visibility only

    // ---- PV: 4 rows x 4 d-cols, packed f32x2 over d-pairs ----
    ull o2[4][2];
#pragma unroll
    for (int j = 0; j < 4; j++) { o2[j][0] = 0ull; o2[j][1] = 0ull; }
    int dd = lane * 4;
#pragma unroll 2
    for (int z0 = 0; z0 < 128; z0 += 4) {
        ulonglong2 vv0 = *(const ulonglong2*)(vs + (z0 + 0) * PAD + dd);
        ulonglong2 vv1 = *(const ulonglong2*)(vs + (z0 + 1) * PAD + dd);
        ulonglong2 vv2 = *(const ulonglong2*)(vs + (z0 + 2) * PAD + dd);
        ulonglong2 vv3 = *(const ulonglong2*)(vs + (z0 + 3) * PAD + dd);
#pragma unroll
        for (int j = 0; j < 4; j++) {
            float4 p4 = *(const float4*)(qs + (warp + 16 * j) * PAD + z0);
            ull pp;
            pp = pack2(p4.x, p4.x); fma2(o2[j][0], pp, vv0.x); fma2(o2[j][1], pp, vv0.y);
            pp = pack2(p4.y, p4.y); fma2(o2[j][0], pp, vv1.x); fma2(o2[j][1], pp, vv1.y);
            pp = pack2(p4.z, p4.z); fma2(o2[j][0], pp, vv2.x); fma2(o2[j][1], pp, vv2.y);
            pp = pack2(p4.w, p4.w); fma2(o2[j][0], pp, vv3.x); fma2(o2[j][1], pp, vv3.y);
        }
    }
#pragma unroll
    for (int j = 0; j < 4; j++) {
        int s = warp + 16 * j;
        float2 a = unpack2(o2[j][0]);
        float2 c = unpack2(o2[j][1]);
        *(float4*)(&g_so[b][n * BS + s][dd]) = make_float4(a.x, a.y, c.x, c.y);
    }
}

// cross-hash-round combine. grid (SL, B), block 128 (one thread per dim)
__global__ void k_combine(float* __restrict__ out) {
    int t = blockIdx.x, b = blockIdx.y;
    int d = threadIdx.x;
    int p[NH];
    float l[NH];
    float m = MNEG;
#pragma unroll
    for (int h = 0; h < NH; h++) {
        p[h] = g_undo[b][h * SL + t];
        l[h] = g_slog[b][p[h]];
        m = fmaxf(m, l[h]);
    }
    float sum = 0.f;
#pragma unroll
    for (int h = 0; h < NH; h++) { l[h] = expf(l[h] - m); sum += l[h]; }
    float inv = 1.f / sum;
    float acc = 0.f;
#pragma unroll
    for (int h = 0; h < NH; h++) acc += l[h] * inv * g_so[b][p[h]][d];
    out[((size_t)b * SL + t) * D + d] = acc;
}

// ---------------- launch ----------------------------------------------------
extern "C" void kernel_launch(void* const* d_in, const int* in_sizes, int n_in,
                              void* d_out, int out_size) {
    (void)in_sizes; (void)n_in; (void)out_size;
    const float* qk  = (const float*)d_in[0];
    const float* v   = (const float*)d_in[1];
    const float* rot = (const float*)d_in[2];
    float* out = (float*)d_out;

    // floats: (64+128+128)*PAD ; ints: 64+64+128+128+512+128*18 = 3200
    const int smem_bytes = (320 * PAD) * 4 + 3200 * 4;  // 181,760 B
    cudaFuncSetAttribute(k_attn, cudaFuncAttributeMaxDynamicSharedMemorySize, smem_bytes);

    k_zero_hist<<<B, NC>>>();
    k_buckets<<<dim3(SL / 256, NH, B), 256>>>(qk, rot);
    k_prefix<<<B, NC>>>();
    k_scatter<<<dim3(NC, B), 128>>>();
    k_loc<<<(B * NSL) / 256, 256>>>();
    k_attn<<<dim3(NC, B), 512, smem_bytes>>>(qk, v);
    k_combine<<<dim3(SL, B), 128>>>(out);
}